// round 14
// baseline (speedup 1.0000x reference)
#include <cuda_runtime.h>
#include <cuda_fp16.h>
#include <cstdint>

// CausalAttention B=4, S=2048, D=1024 — mma.sync fp16x2 emulated-fp32.
// Split planes precomputed in gmem; GEMM staging = raw 16B copies; B via ldmatrix.
// d_out = [ context (4*2048*1024 f32) | attn_scores (4*2048*2048 f32) ]

#define Bb 4
#define Ss 2048
#define Dd 1024
#define BSs (Bb*Ss)

// fp16 split planes (value = plane0 + plane1 exactly to fp16x2 precision)
__device__ __half g_Xh [2][(size_t)BSs * Dd];          // [tok][d]
__device__ __half g_Wth[2][(size_t)3 * Dd * Dd];       // [ncat][k]  (W transposed)
__device__ __half g_Qh [2][(size_t)BSs * Dd];          // [tok][d]
__device__ __half g_Kh [2][(size_t)BSs * Dd];          // [tok][d]
__device__ __half g_Vth[2][(size_t)Bb * Dd * Ss];      // [b][d][tok] (V transposed)
__device__ __half g_Ph [2][(size_t)Bb * Ss * Ss];      // [b][q][tok] (zero-padded)
__device__ float  g_V  [(size_t)BSs * Dd];             // fp32 V (input to transpose)

#define BM 128
#define BN 128
#define BK 32
#define NT 512
#define KPAD 40                        // halves per plane row
#define PLANEH (BM * KPAD)             // 5120 halves
#define SMEM_BYTES (2 * 4 * PLANEH * 2)   // 2 bufs x 4 planes = 81920 B

__device__ __forceinline__ uint32_t smem_u32(const void* p) {
    uint32_t a;
    asm("{ .reg .u64 t; cvta.to.shared.u64 t, %1; cvt.u32.u64 %0, t; }" : "=r"(a) : "l"(p));
    return a;
}

__device__ __forceinline__ void ldsm_x4(uint32_t* a, uint32_t addr) {
    asm volatile("ldmatrix.sync.aligned.m8n8.x4.shared.b16 {%0,%1,%2,%3}, [%4];"
                 : "=r"(a[0]), "=r"(a[1]), "=r"(a[2]), "=r"(a[3]) : "r"(addr));
}

__device__ __forceinline__ void mma16816(float* d, const uint32_t* a, const uint32_t* b) {
    asm volatile(
        "mma.sync.aligned.m16n8k16.row.col.f32.f16.f16.f32 "
        "{%0,%1,%2,%3}, {%4,%5,%6,%7}, {%8,%9}, {%0,%1,%2,%3};"
        : "+f"(d[0]), "+f"(d[1]), "+f"(d[2]), "+f"(d[3])
        : "r"(a[0]), "r"(a[1]), "r"(a[2]), "r"(a[3]), "r"(b[0]), "r"(b[1]));
}

__device__ __forceinline__ void split2(float v, __half& h0, __half& h1) {
    h0 = __float2half_rn(v);
    h1 = __float2half_rn(v - __half2float(h0));
}

// ---------------------------------------------------------------------------
// GEMM core: C(128x128) += A . B^T on precomputed half planes.
// A planes: [m][lda] (k contiguous). B planes: [n][ldb] (k contiguous).
// 512 threads, 16 warps in 4x4 grid of 32x32 tiles; double-buffered smem.
// Staging: per chunk per thread 4x (LDG.128 + STS.128).
// ---------------------------------------------------------------------------
__device__ __forceinline__ void mma_gemm(__half* sm,
                                         const __half* __restrict__ A0,
                                         const __half* __restrict__ A1, size_t lda,
                                         const __half* __restrict__ B0,
                                         const __half* __restrict__ B1, size_t ldb,
                                         int NB, float acc[2][4][4])
{
    const int tid  = threadIdx.x;
    const int lane = tid & 31;
    const int wid  = tid >> 5;
    const int wm   = (wid & 3) * 32;
    const int wn   = (wid >> 2) * 32;

    // staging map: row r = tid>>2 (0..127), seg = (tid&3)*8 halves (16B)
    const int rS  = tid >> 2;
    const int sS  = (tid & 3) * 8;

    const __half* src[4] = {
        A0 + (size_t)rS * lda + sS,
        A1 + (size_t)rS * lda + sS,
        B0 + (size_t)rS * ldb + sS,
        B1 + (size_t)rS * ldb + sS
    };

    uint4 pf[4];

    auto load_chunk = [&](int c) {
        const size_t ko = (size_t)c * BK;
        #pragma unroll
        for (int p = 0; p < 4; p++)
            pf[p] = *(const uint4*)(src[p] + ko);
    };
    auto store_chunk = [&](int buf) {
        #pragma unroll
        for (int p = 0; p < 4; p++)
            *(uint4*)(sm + (size_t)(buf*4 + p) * PLANEH + rS * KPAD + sS) = pf[p];
    };

    load_chunk(0);
    store_chunk(0);
    __syncthreads();

    for (int c = 0; c < NB; c++) {
        const int buf = c & 1;
        const bool next = (c + 1 < NB);
        if (next) load_chunk(c + 1);

        // ---- compute on buf ----
        {
            const uint32_t aB0 = smem_u32(sm + (size_t)(buf*4 + 0) * PLANEH);
            const uint32_t aB1 = smem_u32(sm + (size_t)(buf*4 + 1) * PLANEH);
            const uint32_t bB0 = smem_u32(sm + (size_t)(buf*4 + 2) * PLANEH);
            const uint32_t bB1 = smem_u32(sm + (size_t)(buf*4 + 3) * PLANEH);

            #pragma unroll
            for (int ks = 0; ks < 2; ks++) {
                // A fragments (16 rows x 16 k per ldsm.x4)
                uint32_t afr[2][2][4];
                const int arow = wm + (lane & 15);
                const int acol = ks*16 + (lane >> 4) * 8;
                #pragma unroll
                for (int im = 0; im < 2; im++) {
                    ldsm_x4(afr[0][im], aB0 + (uint32_t)((arow + im*16)*KPAD + acol)*2);
                    ldsm_x4(afr[1][im], aB1 + (uint32_t)((arow + im*16)*KPAD + acol)*2);
                }
                // B fragments via ldmatrix: mat = lane>>3:
                //   n = wn + g*16 + (mat>>1)*8 + (lane&7), k = ks*16 + (mat&1)*8
                uint32_t bfr[2][4][2];
                const int brow = lane & 7;
                const int bm   = lane >> 3;
                const int bn_o = ((bm >> 1) << 3) + brow;    // row within 16-n group
                const int bk_o = ks*16 + ((bm & 1) << 3);
                #pragma unroll
                for (int g = 0; g < 2; g++) {
                    const uint32_t off =
                        (uint32_t)((wn + g*16 + bn_o) * KPAD + bk_o) * 2;
                    uint32_t t0[4], t1[4];
                    ldsm_x4(t0, bB0 + off);
                    ldsm_x4(t1, bB1 + off);
                    bfr[0][g*2 + 0][0] = t0[0]; bfr[0][g*2 + 0][1] = t0[1];
                    bfr[0][g*2 + 1][0] = t0[2]; bfr[0][g*2 + 1][1] = t0[3];
                    bfr[1][g*2 + 0][0] = t1[0]; bfr[1][g*2 + 0][1] = t1[1];
                    bfr[1][g*2 + 1][0] = t1[2]; bfr[1][g*2 + 1][1] = t1[3];
                }
                #pragma unroll
                for (int im = 0; im < 2; im++)
                    #pragma unroll
                    for (int in_ = 0; in_ < 4; in_++) {
                        mma16816(acc[im][in_], afr[0][im], bfr[0][in_]);  // a0*b0
                        mma16816(acc[im][in_], afr[1][im], bfr[0][in_]);  // a1*b0
                        mma16816(acc[im][in_], afr[0][im], bfr[1][in_]);  // a0*b1
                    }
            }
        }

        if (next) store_chunk(buf ^ 1);
        __syncthreads();
    }
}

// ---------------------------------------------------------------------------
// Split kernels
// ---------------------------------------------------------------------------
__global__ __launch_bounds__(256) void split_x(const float* __restrict__ X)
{
    const size_t i = ((size_t)blockIdx.x * 256 + threadIdx.x) * 8;
    float4 v0 = *(const float4*)&X[i];
    float4 v1 = *(const float4*)&X[i + 4];
    const float v[8] = {v0.x, v0.y, v0.z, v0.w, v1.x, v1.y, v1.z, v1.w};
    __half h0[8], h1[8];
    #pragma unroll
    for (int j = 0; j < 8; j++) split2(v[j], h0[j], h1[j]);
    uint4 u0, u1;
    __half2* p0 = (__half2*)&u0;  __half2* p1 = (__half2*)&u1;
    #pragma unroll
    for (int j = 0; j < 4; j++) {
        p0[j] = __halves2half2(h0[2*j], h0[2*j+1]);
        p1[j] = __halves2half2(h1[2*j], h1[2*j+1]);
    }
    *(uint4*)&g_Xh[0][i] = u0;
    *(uint4*)&g_Xh[1][i] = u1;
}

__global__ __launch_bounds__(256) void split_wT(
    const float* __restrict__ Wq, const float* __restrict__ Wk,
    const float* __restrict__ Wv)
{
    __shared__ float s[32][33];
    const int w = blockIdx.z;
    const float* W = (w == 0) ? Wq : (w == 1) ? Wk : Wv;
    const int n0 = blockIdx.x * 32, k0 = blockIdx.y * 32;
    const int tx = threadIdx.x & 31, ty = threadIdx.x >> 5;   // (32, 8)
    #pragma unroll
    for (int i = 0; i < 4; i++)
        s[ty + i*8][tx] = W[(size_t)(k0 + ty + i*8) * Dd + n0 + tx];
    __syncthreads();
    #pragma unroll
    for (int i = 0; i < 4; i++) {
        const int n = n0 + ty + i*8;
        __half h0, h1; split2(s[tx][ty + i*8], h0, h1);
        const size_t o = (size_t)(w * Dd + n) * Dd + k0 + tx;
        g_Wth[0][o] = h0; g_Wth[1][o] = h1;
    }
}

__global__ __launch_bounds__(256) void split_vT()
{
    __shared__ float s[32][33];
    const int b = blockIdx.z;
    const int tok0 = blockIdx.x * 32, d0 = blockIdx.y * 32;
    const int tx = threadIdx.x & 31, ty = threadIdx.x >> 5;
    #pragma unroll
    for (int i = 0; i < 4; i++)
        s[ty + i*8][tx] = g_V[((size_t)b * Ss + tok0 + ty + i*8) * Dd + d0 + tx];
    __syncthreads();
    #pragma unroll
    for (int i = 0; i < 4; i++) {
        const int d = d0 + ty + i*8;
        __half h0, h1; split2(s[tx][ty + i*8], h0, h1);
        const size_t o = (size_t)b * Dd * Ss + (size_t)d * Ss + tok0 + tx;
        g_Vth[0][o] = h0; g_Vth[1][o] = h1;
    }
}

// ---------------------------------------------------------------------------
// Kernel: QKV projection. widx 0/1 -> write Qh/Kh split planes; widx 2 -> fp32 V.
// ---------------------------------------------------------------------------
__global__ __launch_bounds__(NT) void qkv_mma()
{
    extern __shared__ __half sm[];

    const int n0g  = blockIdx.x * BN;
    const int m0   = blockIdx.y * BM;
    const int widx = n0g >> 10;
    const int col0 = n0g & 1023;

    float acc[2][4][4] = {};
    mma_gemm(sm,
        g_Xh[0] + (size_t)m0 * Dd, g_Xh[1] + (size_t)m0 * Dd, Dd,
        g_Wth[0] + (size_t)n0g * Dd, g_Wth[1] + (size_t)n0g * Dd, Dd,
        Dd / BK, acc);

    const int lane = threadIdx.x & 31, wid = threadIdx.x >> 5;
    const int rb = m0 + (wid & 3)*32, cb = col0 + (wid >> 2)*32;

    if (widx < 2) {
        __half* O0 = widx ? g_Kh[0] : g_Qh[0];
        __half* O1 = widx ? g_Kh[1] : g_Qh[1];
        #pragma unroll
        for (int im = 0; im < 2; im++)
            #pragma unroll
            for (int in_ = 0; in_ < 4; in_++) {
                const int r0 = rb + im*16 + (lane >> 2);
                const int c0 = cb + in_*8 + (lane & 3)*2;
                __half a0, a1, b0, b1;
                split2(acc[im][in_][0], a0, a1);
                split2(acc[im][in_][1], b0, b1);
                *(__half2*)&O0[(size_t)r0 * Dd + c0] = __halves2half2(a0, b0);
                *(__half2*)&O1[(size_t)r0 * Dd + c0] = __halves2half2(a1, b1);
                split2(acc[im][in_][2], a0, a1);
                split2(acc[im][in_][3], b0, b1);
                *(__half2*)&O0[(size_t)(r0 + 8) * Dd + c0] = __halves2half2(a0, b0);
                *(__half2*)&O1[(size_t)(r0 + 8) * Dd + c0] = __halves2half2(a1, b1);
            }
    } else {
        #pragma unroll
        for (int im = 0; im < 2; im++)
            #pragma unroll
            for (int in_ = 0; in_ < 4; in_++) {
                const int r0 = rb + im*16 + (lane >> 2);
                const int c0 = col0 + (wid >> 2)*32 + in_*8 + (lane & 3)*2;
                float2 v0 = {acc[im][in_][0], acc[im][in_][1]};
                float2 v1 = {acc[im][in_][2], acc[im][in_][3]};
                *(float2*)&g_V[(size_t)r0 * Dd + c0]       = v0;
                *(float2*)&g_V[(size_t)(r0 + 8) * Dd + c0] = v1;
            }
    }
}

// ---------------------------------------------------------------------------
// Kernel: scores = (Q.K^T)/32, causal masked.
// ---------------------------------------------------------------------------
__global__ __launch_bounds__(NT) void scores_mma(float* __restrict__ Sout)
{
    extern __shared__ __half sm[];

    const int b  = blockIdx.z;
    const int q0 = blockIdx.y * BM;
    const int k0 = blockIdx.x * BN;
    const int tid = threadIdx.x;
    float* Sb = Sout + (size_t)b * Ss * Ss;

    if (k0 > q0 + 127) {                       // fully masked tile
        const float4 z = {0.f, 0.f, 0.f, 0.f};
        for (int t = tid; t < 4096; t += NT) {
            const int r = t >> 5, c4 = (t & 31) * 4;
            *(float4*)&Sb[(size_t)(q0 + r) * Ss + k0 + c4] = z;
        }
        return;
    }

    const size_t oq = ((size_t)b * Ss + q0) * Dd;
    const size_t ok = ((size_t)b * Ss + k0) * Dd;
    float acc[2][4][4] = {};
    mma_gemm(sm, g_Qh[0] + oq, g_Qh[1] + oq, Dd,
                 g_Kh[0] + ok, g_Kh[1] + ok, Dd, Dd / BK, acc);

    const float scale = 0.03125f;
    const int lane = tid & 31, wid = tid >> 5;
    const int wm = (wid & 3) * 32, wn = (wid >> 2) * 32;
    #pragma unroll
    for (int im = 0; im < 2; im++)
        #pragma unroll
        for (int in_ = 0; in_ < 4; in_++) {
            const int q  = q0 + wm + im*16 + (lane >> 2);
            const int kk = k0 + wn + in_*8 + (lane & 3)*2;
            float2 v0, v1;
            v0.x = (kk   <= q)     ? acc[im][in_][0] * scale : 0.f;
            v0.y = (kk+1 <= q)     ? acc[im][in_][1] * scale : 0.f;
            v1.x = (kk   <= q + 8) ? acc[im][in_][2] * scale : 0.f;
            v1.y = (kk+1 <= q + 8) ? acc[im][in_][3] * scale : 0.f;
            *(float2*)&Sb[(size_t)q * Ss + kk]       = v0;
            *(float2*)&Sb[(size_t)(q + 8) * Ss + kk] = v1;
        }
}

// ---------------------------------------------------------------------------
// Kernel: causal row softmax in place + write P split planes (zero padded).
// ---------------------------------------------------------------------------
__global__ __launch_bounds__(256) void softmax_kernel(float* __restrict__ Sc)
{
    const int row = blockIdx.x;
    const int b = row / Ss;
    const int q = row - b * Ss;
    float* r = Sc + (size_t)b * Ss * Ss + (size_t)q * Ss;
    const size_t pb = ((size_t)b * Ss + q) * Ss;
    const int len = q + 1;
    const int t = threadIdx.x;

    __shared__ float red[256];

    float vals[8];
    int n = 0;
    float m = -3.4e38f;
    for (int i = t; i < len; i += 256) { float v = r[i]; vals[n++] = v; m = fmaxf(m, v); }
    red[t] = m; __syncthreads();
    #pragma unroll
    for (int s2 = 128; s2 > 0; s2 >>= 1) {
        if (t < s2) red[t] = fmaxf(red[t], red[t + s2]);
        __syncthreads();
    }
    m = red[0]; __syncthreads();

    float sum = 0.f;
    for (int i = 0; i < n; i++) { vals[i] = __expf(vals[i] - m); sum += vals[i]; }
    red[t] = sum; __syncthreads();
    #pragma unroll
    for (int s2 = 128; s2 > 0; s2 >>= 1) {
        if (t < s2) red[t] += red[t + s2];
        __syncthreads();
    }
    const float inv = 1.0f / red[0];

    n = 0;
    for (int i = t; i < Ss; i += 256) {
        float pv = 0.0f;
        if (i < len) { pv = vals[n++] * inv; r[i] = pv; }
        __half h0, h1; split2(pv, h0, h1);
        g_Ph[0][pb + i] = h0; g_Ph[1][pb + i] = h1;
    }
}

// ---------------------------------------------------------------------------
// Kernel: context = P @ V^T-planes  (K loop stops past diagonal q-block).
// ---------------------------------------------------------------------------
__global__ __launch_bounds__(NT) void context_mma(float* __restrict__ Ctx)
{
    extern __shared__ __half sm[];

    const int b  = blockIdx.z;
    const int q0 = blockIdx.y * BM;
    const int n0 = blockIdx.x * BN;

    const size_t op = ((size_t)b * Ss + q0) * Ss;
    const size_t ov = (size_t)b * Dd * Ss + (size_t)n0 * Ss;
    float acc[2][4][4] = {};
    mma_gemm(sm, g_Ph[0] + op, g_Ph[1] + op, Ss,
                 g_Vth[0] + ov, g_Vth[1] + ov, Ss, q0 / BK + 4, acc);

    float* Ob = Ctx + (size_t)b * Ss * Dd;
    const int lane = threadIdx.x & 31, wid = threadIdx.x >> 5;
    const int rb = q0 + (wid & 3)*32, cb = n0 + (wid >> 2)*32;
    #pragma unroll
    for (int im = 0; im < 2; im++)
        #pragma unroll
        for (int in_ = 0; in_ < 4; in_++) {
            const int r0 = rb + im*16 + (lane >> 2);
            const int c0 = cb + in_*8 + (lane & 3)*2;
            float2 v0 = {acc[im][in_][0], acc[im][in_][1]};
            float2 v1 = {acc[im][in_][2], acc[im][in_][3]};
            *(float2*)&Ob[(size_t)r0 * Dd + c0]       = v0;
            *(float2*)&Ob[(size_t)(r0 + 8) * Dd + c0] = v1;
        }
}

// ---------------------------------------------------------------------------
extern "C" void kernel_launch(void* const* d_in, const int* in_sizes, int n_in,
                              void* d_out, int out_size)
{
    const float* x  = (const float*)d_in[0];
    const float* Wq = (const float*)d_in[1];
    const float* Wk = (const float*)d_in[2];
    const float* Wv = (const float*)d_in[3];

    float* out = (float*)d_out;
    float* ctx = out;
    float* sc  = out + (size_t)Bb * Ss * Dd;

    cudaFuncSetAttribute(qkv_mma,     cudaFuncAttributeMaxDynamicSharedMemorySize, SMEM_BYTES);
    cudaFuncSetAttribute(scores_mma,  cudaFuncAttributeMaxDynamicSharedMemorySize, SMEM_BYTES);
    cudaFuncSetAttribute(context_mma, cudaFuncAttributeMaxDynamicSharedMemorySize, SMEM_BYTES);

    split_x<<<(int)(((size_t)BSs * Dd / 8) / 256), 256>>>(x);
    split_wT<<<dim3(Dd/32, Dd/32, 3), 256>>>(Wq, Wk, Wv);

    qkv_mma<<<dim3(3 * Dd / BN, BSs / BM), NT, SMEM_BYTES>>>();
    split_vT<<<dim3(Ss/32, Dd/32, Bb), 256>>>();
    scores_mma<<<dim3(Ss / BN, Ss / BM, Bb), NT, SMEM_BYTES>>>(sc);
    softmax_kernel<<<BSs, 256>>>(sc);
    context_mma<<<dim3(Dd / BN, Ss / BM, Bb), NT, SMEM_BYTES>>>(ctx);
}

// round 15
// speedup vs baseline: 1.0893x; 1.0893x over previous
#include <cuda_runtime.h>
#include <cuda_fp16.h>
#include <cstdint>

// CausalAttention B=4, S=2048, D=1024 — mma.sync fp16x2 emulated-fp32.
// Precomputed split planes + cp.async staging; context GEMM runs 2-pass
// (P single fp16 plane). d_out = [ context | attn_scores ].

#define Bb 4
#define Ss 2048
#define Dd 1024
#define BSs (Bb*Ss)

__device__ __half g_Xh [2][(size_t)BSs * Dd];          // [tok][d]
__device__ __half g_Wth[2][(size_t)3 * Dd * Dd];       // [ncat][k]
__device__ __half g_Qh [2][(size_t)BSs * Dd];
__device__ __half g_Kh [2][(size_t)BSs * Dd];
__device__ __half g_Vth[2][(size_t)Bb * Dd * Ss];      // [b][d][tok]
__device__ __half g_Ph0[(size_t)Bb * Ss * Ss];         // fp16 P, zero-padded
__device__ float  g_V  [(size_t)BSs * Dd];

#define BM 128
#define BN 128
#define BK 32
#define NT 512
#define KPAD 40
#define PLANEH (BM * KPAD)             // 5120 halves = 10240 B
#define SMEM_BYTES (2 * 4 * PLANEH * 2)   // max: 2 bufs x 4 planes

__device__ __forceinline__ uint32_t smem_u32(const void* p) {
    uint32_t a;
    asm("{ .reg .u64 t; cvta.to.shared.u64 t, %1; cvt.u32.u64 %0, t; }" : "=r"(a) : "l"(p));
    return a;
}

__device__ __forceinline__ void cp16(uint32_t dst, const void* src) {
    asm volatile("cp.async.cg.shared.global [%0], [%1], 16;" :: "r"(dst), "l"(src));
}
__device__ __forceinline__ void cp_commit() { asm volatile("cp.async.commit_group;"); }
__device__ __forceinline__ void cp_wait1()  { asm volatile("cp.async.wait_group 1;"); }
__device__ __forceinline__ void cp_wait0()  { asm volatile("cp.async.wait_group 0;"); }

__device__ __forceinline__ void ldsm_x4(uint32_t* a, uint32_t addr) {
    asm volatile("ldmatrix.sync.aligned.m8n8.x4.shared.b16 {%0,%1,%2,%3}, [%4];"
                 : "=r"(a[0]), "=r"(a[1]), "=r"(a[2]), "=r"(a[3]) : "r"(addr));
}

__device__ __forceinline__ void mma16816(float* d, const uint32_t* a, const uint32_t* b) {
    asm volatile(
        "mma.sync.aligned.m16n8k16.row.col.f32.f16.f16.f32 "
        "{%0,%1,%2,%3}, {%4,%5,%6,%7}, {%8,%9}, {%0,%1,%2,%3};"
        : "+f"(d[0]), "+f"(d[1]), "+f"(d[2]), "+f"(d[3])
        : "r"(a[0]), "r"(a[1]), "r"(a[2]), "r"(a[3]), "r"(b[0]), "r"(b[1]));
}

__device__ __forceinline__ void split2(float v, __half& h0, __half& h1) {
    h0 = __float2half_rn(v);
    h1 = __float2half_rn(v - __half2float(h0));
}

// ---------------------------------------------------------------------------
// GEMM core on precomputed half planes. AP = number of A planes (1 or 2).
// Passes: a0b0 [, a1b0 if AP==2], a0b1.  cp.async staging, double buffered.
// 512 threads, 16 warps, 32x32 warp tiles.
// ---------------------------------------------------------------------------
template <int AP>
__device__ __forceinline__ void mma_gemm(__half* sm,
                                         const __half* __restrict__ A0,
                                         const __half* __restrict__ A1, size_t lda,
                                         const __half* __restrict__ B0,
                                         const __half* __restrict__ B1, size_t ldb,
                                         int NB, float acc[2][4][4])
{
    constexpr int NP = AP + 2;
    const int tid  = threadIdx.x;
    const int lane = tid & 31;
    const int wid  = tid >> 5;
    const int wm   = (wid & 3) * 32;
    const int wn   = (wid >> 2) * 32;

    // staging map: row rS = tid>>2 (0..127), segment sS = (tid&3)*8 halves (16B)
    const int rS = tid >> 2;
    const int sS = (tid & 3) * 8;

    const __half* srcs[NP];
    srcs[0] = A0 + (size_t)rS * lda + sS;
    if (AP == 2) srcs[1] = A1 + (size_t)rS * lda + sS;
    srcs[AP + 0] = B0 + (size_t)rS * ldb + sS;
    srcs[AP + 1] = B1 + (size_t)rS * ldb + sS;

    const uint32_t sbase = smem_u32(sm);
    const uint32_t stOff = (uint32_t)(rS * KPAD + sS) * 2;

    auto issue_chunk = [&](int c, int buf) {
        const size_t ko = (size_t)c * BK;
        #pragma unroll
        for (int p = 0; p < NP; p++)
            cp16(sbase + (uint32_t)((buf * NP + p) * PLANEH) * 2 + stOff,
                 srcs[p] + ko);
        cp_commit();
    };

    issue_chunk(0, 0);

    for (int c = 0; c < NB; c++) {
        const int buf = c & 1;
        const bool next = (c + 1 < NB);
        if (next) { issue_chunk(c + 1, buf ^ 1); cp_wait1(); }
        else      { cp_wait0(); }
        __syncthreads();                      // chunk c visible to all threads

        // ---- compute on buf ----
        {
            const uint32_t aB0 = sbase + (uint32_t)((buf * NP + 0) * PLANEH) * 2;
            const uint32_t aB1 = sbase + (uint32_t)((buf * NP + 1) * PLANEH) * 2;  // AP==2
            const uint32_t bB0 = sbase + (uint32_t)((buf * NP + AP + 0) * PLANEH) * 2;
            const uint32_t bB1 = sbase + (uint32_t)((buf * NP + AP + 1) * PLANEH) * 2;

            #pragma unroll
            for (int ks = 0; ks < 2; ks++) {
                uint32_t afr[2][2][4];
                const int arow = wm + (lane & 15);
                const int acol = ks*16 + (lane >> 4) * 8;
                #pragma unroll
                for (int im = 0; im < 2; im++) {
                    ldsm_x4(afr[0][im], aB0 + (uint32_t)((arow + im*16)*KPAD + acol)*2);
                    if (AP == 2)
                        ldsm_x4(afr[1][im], aB1 + (uint32_t)((arow + im*16)*KPAD + acol)*2);
                }
                uint32_t bfr[2][4][2];
                const int brow = lane & 7;
                const int bm   = lane >> 3;
                const int bn_o = ((bm >> 1) << 3) + brow;
                const int bk_o = ks*16 + ((bm & 1) << 3);
                #pragma unroll
                for (int g = 0; g < 2; g++) {
                    const uint32_t off = (uint32_t)((wn + g*16 + bn_o) * KPAD + bk_o) * 2;
                    uint32_t t0[4], t1[4];
                    ldsm_x4(t0, bB0 + off);
                    ldsm_x4(t1, bB1 + off);
                    bfr[0][g*2 + 0][0] = t0[0]; bfr[0][g*2 + 0][1] = t0[1];
                    bfr[0][g*2 + 1][0] = t0[2]; bfr[0][g*2 + 1][1] = t0[3];
                    bfr[1][g*2 + 0][0] = t1[0]; bfr[1][g*2 + 0][1] = t1[1];
                    bfr[1][g*2 + 1][0] = t1[2]; bfr[1][g*2 + 1][1] = t1[3];
                }
                #pragma unroll
                for (int im = 0; im < 2; im++)
                    #pragma unroll
                    for (int in_ = 0; in_ < 4; in_++) {
                        mma16816(acc[im][in_], afr[0][im], bfr[0][in_]);     // a0*b0
                        if (AP == 2)
                            mma16816(acc[im][in_], afr[1][im], bfr[0][in_]); // a1*b0
                        mma16816(acc[im][in_], afr[0][im], bfr[1][in_]);     // a0*b1
                    }
            }
        }
        __syncthreads();   // compute done before buf is overwritten next iter
    }
}

// ---------------------------------------------------------------------------
// Split kernels
// ---------------------------------------------------------------------------
__global__ __launch_bounds__(256) void split_x(const float* __restrict__ X)
{
    const size_t i = ((size_t)blockIdx.x * 256 + threadIdx.x) * 8;
    float4 v0 = *(const float4*)&X[i];
    float4 v1 = *(const float4*)&X[i + 4];
    const float v[8] = {v0.x, v0.y, v0.z, v0.w, v1.x, v1.y, v1.z, v1.w};
    __half h0[8], h1[8];
    #pragma unroll
    for (int j = 0; j < 8; j++) split2(v[j], h0[j], h1[j]);
    uint4 u0, u1;
    __half2* p0 = (__half2*)&u0;  __half2* p1 = (__half2*)&u1;
    #pragma unroll
    for (int j = 0; j < 4; j++) {
        p0[j] = __halves2half2(h0[2*j], h0[2*j+1]);
        p1[j] = __halves2half2(h1[2*j], h1[2*j+1]);
    }
    *(uint4*)&g_Xh[0][i] = u0;
    *(uint4*)&g_Xh[1][i] = u1;
}

__global__ __launch_bounds__(256) void split_wT(
    const float* __restrict__ Wq, const float* __restrict__ Wk,
    const float* __restrict__ Wv)
{
    __shared__ float s[32][33];
    const int w = blockIdx.z;
    const float* W = (w == 0) ? Wq : (w == 1) ? Wk : Wv;
    const int n0 = blockIdx.x * 32, k0 = blockIdx.y * 32;
    const int tx = threadIdx.x & 31, ty = threadIdx.x >> 5;
    #pragma unroll
    for (int i = 0; i < 4; i++)
        s[ty + i*8][tx] = W[(size_t)(k0 + ty + i*8) * Dd + n0 + tx];
    __syncthreads();
    #pragma unroll
    for (int i = 0; i < 4; i++) {
        const int n = n0 + ty + i*8;
        __half h0, h1; split2(s[tx][ty + i*8], h0, h1);
        const size_t o = (size_t)(w * Dd + n) * Dd + k0 + tx;
        g_Wth[0][o] = h0; g_Wth[1][o] = h1;
    }
}

__global__ __launch_bounds__(256) void split_vT()
{
    __shared__ float s[32][33];
    const int b = blockIdx.z;
    const int tok0 = blockIdx.x * 32, d0 = blockIdx.y * 32;
    const int tx = threadIdx.x & 31, ty = threadIdx.x >> 5;
    #pragma unroll
    for (int i = 0; i < 4; i++)
        s[ty + i*8][tx] = g_V[((size_t)b * Ss + tok0 + ty + i*8) * Dd + d0 + tx];
    __syncthreads();
    #pragma unroll
    for (int i = 0; i < 4; i++) {
        const int d = d0 + ty + i*8;
        __half h0, h1; split2(s[tx][ty + i*8], h0, h1);
        const size_t o = (size_t)b * Dd * Ss + (size_t)d * Ss + tok0 + tx;
        g_Vth[0][o] = h0; g_Vth[1][o] = h1;
    }
}

// ---------------------------------------------------------------------------
// Kernel: QKV projection (3-pass).
// ---------------------------------------------------------------------------
__global__ __launch_bounds__(NT) void qkv_mma()
{
    extern __shared__ __half sm[];

    const int n0g  = blockIdx.x * BN;
    const int m0   = blockIdx.y * BM;
    const int widx = n0g >> 10;
    const int col0 = n0g & 1023;

    float acc[2][4][4] = {};
    mma_gemm<2>(sm,
        g_Xh[0] + (size_t)m0 * Dd, g_Xh[1] + (size_t)m0 * Dd, Dd,
        g_Wth[0] + (size_t)n0g * Dd, g_Wth[1] + (size_t)n0g * Dd, Dd,
        Dd / BK, acc);

    const int lane = threadIdx.x & 31, wid = threadIdx.x >> 5;
    const int rb = m0 + (wid & 3)*32, cb = col0 + (wid >> 2)*32;

    if (widx < 2) {
        __half* O0 = widx ? g_Kh[0] : g_Qh[0];
        __half* O1 = widx ? g_Kh[1] : g_Qh[1];
        #pragma unroll
        for (int im = 0; im < 2; im++)
            #pragma unroll
            for (int in_ = 0; in_ < 4; in_++) {
                const int r0 = rb + im*16 + (lane >> 2);
                const int c0 = cb + in_*8 + (lane & 3)*2;
                __half a0, a1, b0, b1;
                split2(acc[im][in_][0], a0, a1);
                split2(acc[im][in_][1], b0, b1);
                *(__half2*)&O0[(size_t)r0 * Dd + c0] = __halves2half2(a0, b0);
                *(__half2*)&O1[(size_t)r0 * Dd + c0] = __halves2half2(a1, b1);
                split2(acc[im][in_][2], a0, a1);
                split2(acc[im][in_][3], b0, b1);
                *(__half2*)&O0[(size_t)(r0 + 8) * Dd + c0] = __halves2half2(a0, b0);
                *(__half2*)&O1[(size_t)(r0 + 8) * Dd + c0] = __halves2half2(a1, b1);
            }
    } else {
        #pragma unroll
        for (int im = 0; im < 2; im++)
            #pragma unroll
            for (int in_ = 0; in_ < 4; in_++) {
                const int r0 = rb + im*16 + (lane >> 2);
                const int c0 = cb + in_*8 + (lane & 3)*2;
                float2 v0 = {acc[im][in_][0], acc[im][in_][1]};
                float2 v1 = {acc[im][in_][2], acc[im][in_][3]};
                *(float2*)&g_V[(size_t)r0 * Dd + c0]       = v0;
                *(float2*)&g_V[(size_t)(r0 + 8) * Dd + c0] = v1;
            }
    }
}

// ---------------------------------------------------------------------------
// Kernel: scores = (Q.K^T)/32, causal masked (3-pass).
// ---------------------------------------------------------------------------
__global__ __launch_bounds__(NT) void scores_mma(float* __restrict__ Sout)
{
    extern __shared__ __half sm[];

    const int b  = blockIdx.z;
    const int q0 = blockIdx.y * BM;
    const int k0 = blockIdx.x * BN;
    const int tid = threadIdx.x;
    float* Sb = Sout + (size_t)b * Ss * Ss;

    if (k0 > q0 + 127) {
        const float4 z = {0.f, 0.f, 0.f, 0.f};
        for (int t = tid; t < 4096; t += NT) {
            const int r = t >> 5, c4 = (t & 31) * 4;
            *(float4*)&Sb[(size_t)(q0 + r) * Ss + k0 + c4] = z;
        }
        return;
    }

    const size_t oq = ((size_t)b * Ss + q0) * Dd;
    const size_t ok = ((size_t)b * Ss + k0) * Dd;
    float acc[2][4][4] = {};
    mma_gemm<2>(sm, g_Qh[0] + oq, g_Qh[1] + oq, Dd,
                    g_Kh[0] + ok, g_Kh[1] + ok, Dd, Dd / BK, acc);

    const float scale = 0.03125f;
    const int lane = tid & 31, wid = tid >> 5;
    const int wm = (wid & 3) * 32, wn = (wid >> 2) * 32;
    #pragma unroll
    for (int im = 0; im < 2; im++)
        #pragma unroll
        for (int in_ = 0; in_ < 4; in_++) {
            const int q  = q0 + wm + im*16 + (lane >> 2);
            const int kk = k0 + wn + in_*8 + (lane & 3)*2;
            float2 v0, v1;
            v0.x = (kk   <= q)     ? acc[im][in_][0] * scale : 0.f;
            v0.y = (kk+1 <= q)     ? acc[im][in_][1] * scale : 0.f;
            v1.x = (kk   <= q + 8) ? acc[im][in_][2] * scale : 0.f;
            v1.y = (kk+1 <= q + 8) ? acc[im][in_][3] * scale : 0.f;
            *(float2*)&Sb[(size_t)q * Ss + kk]       = v0;
            *(float2*)&Sb[(size_t)(q + 8) * Ss + kk] = v1;
        }
}

// ---------------------------------------------------------------------------
// Kernel: causal row softmax in place + single fp16 P plane (zero padded).
// ---------------------------------------------------------------------------
__global__ __launch_bounds__(256) void softmax_kernel(float* __restrict__ Sc)
{
    const int row = blockIdx.x;
    const int b = row / Ss;
    const int q = row - b * Ss;
    float* r = Sc + (size_t)b * Ss * Ss + (size_t)q * Ss;
    const size_t pb = ((size_t)b * Ss + q) * Ss;
    const int len = q + 1;
    const int t = threadIdx.x;

    __shared__ float red[256];

    float vals[8];
    int n = 0;
    float m = -3.4e38f;
    for (int i = t; i < len; i += 256) { float v = r[i]; vals[n++] = v; m = fmaxf(m, v); }
    red[t] = m; __syncthreads();
    #pragma unroll
    for (int s2 = 128; s2 > 0; s2 >>= 1) {
        if (t < s2) red[t] = fmaxf(red[t], red[t + s2]);
        __syncthreads();
    }
    m = red[0]; __syncthreads();

    float sum = 0.f;
    for (int i = 0; i < n; i++) { vals[i] = __expf(vals[i] - m); sum += vals[i]; }
    red[t] = sum; __syncthreads();
    #pragma unroll
    for (int s2 = 128; s2 > 0; s2 >>= 1) {
        if (t < s2) red[t] += red[t + s2];
        __syncthreads();
    }
    const float inv = 1.0f / red[0];

    n = 0;
    for (int i = t; i < Ss; i += 256) {
        float pv = 0.0f;
        if (i < len) { pv = vals[n++] * inv; r[i] = pv; }
        g_Ph0[pb + i] = __float2half_rn(pv);
    }
}

// ---------------------------------------------------------------------------
// Kernel: context = P @ V (2-pass: P0*V0 + P0*V1); K loop stops past diagonal.
// ---------------------------------------------------------------------------
__global__ __launch_bounds__(NT) void context_mma(float* __restrict__ Ctx)
{
    extern __shared__ __half sm[];

    const int b  = blockIdx.z;
    const int q0 = blockIdx.y * BM;
    const int n0 = blockIdx.x * BN;

    const size_t op = ((size_t)b * Ss + q0) * Ss;
    const size_t ov = (size_t)b * Dd * Ss + (size_t)n0 * Ss;
    float acc[2][4][4] = {};
    mma_gemm<1>(sm, g_Ph0 + op, (const __half*)nullptr, Ss,
                    g_Vth[0] + ov, g_Vth[1] + ov, Ss, q0 / BK + 4, acc);

    float* Ob = Ctx + (size_t)b * Ss * Dd;
    const int lane = threadIdx.x & 31, wid = threadIdx.x >> 5;
    const int rb = q0 + (wid & 3)*32, cb = n0 + (wid >> 2)*32;
    #pragma unroll
    for (int im = 0; im < 2; im++)
        #pragma unroll
        for (int in_ = 0; in_ < 4; in_++) {
            const int r0 = rb + im*16 + (lane >> 2);
            const int c0 = cb + in_*8 + (lane & 3)*2;
            float2 v0 = {acc[im][in_][0], acc[im][in_][1]};
            float2 v1 = {acc[im][in_][2], acc[im][in_][3]};
            *(float2*)&Ob[(size_t)r0 * Dd + c0]       = v0;
            *(float2*)&Ob[(size_t)(r0 + 8) * Dd + c0] = v1;
        }
}

// ---------------------------------------------------------------------------
extern "C" void kernel_launch(void* const* d_in, const int* in_sizes, int n_in,
                              void* d_out, int out_size)
{
    const float* x  = (const float*)d_in[0];
    const float* Wq = (const float*)d_in[1];
    const float* Wk = (const float*)d_in[2];
    const float* Wv = (const float*)d_in[3];

    float* out = (float*)d_out;
    float* ctx = out;
    float* sc  = out + (size_t)Bb * Ss * Dd;

    cudaFuncSetAttribute(qkv_mma,     cudaFuncAttributeMaxDynamicSharedMemorySize, SMEM_BYTES);
    cudaFuncSetAttribute(scores_mma,  cudaFuncAttributeMaxDynamicSharedMemorySize, SMEM_BYTES);
    cudaFuncSetAttribute(context_mma, cudaFuncAttributeMaxDynamicSharedMemorySize, SMEM_BYTES);

    split_x<<<(int)(((size_t)BSs * Dd / 8) / 256), 256>>>(x);
    split_wT<<<dim3(Dd/32, Dd/32, 3), 256>>>(Wq, Wk, Wv);

    qkv_mma<<<dim3(3 * Dd / BN, BSs / BM), NT, SMEM_BYTES>>>();
    split_vT<<<dim3(Ss/32, Dd/32, Bb), 256>>>();
    scores_mma<<<dim3(Ss / BN, Ss / BM, Bb), NT, SMEM_BYTES>>>(sc);
    softmax_kernel<<<BSs, 256>>>(sc);
    context_mma<<<dim3(Dd / BN, Ss / BM, Bb), NT, SMEM_BYTES>>>(ctx);
}

// round 16
// speedup vs baseline: 1.1663x; 1.0706x over previous
#include <cuda_runtime.h>
#include <cuda_fp16.h>
#include <cstdint>

// CausalAttention B=4, S=2048, D=1024 — mma.sync fp16x2 emulated-fp32.
// 3-stage cp.async ring (1 sync/chunk); QKV/scores 3-pass, context 1-pass
// (fp16 P one-hot-exact, fp16 V). d_out = [ context | attn_scores ].

#define Bb 4
#define Ss 2048
#define Dd 1024
#define BSs (Bb*Ss)

__device__ __half g_Xh [2][(size_t)BSs * Dd];          // [tok][d]
__device__ __half g_Wth[2][(size_t)3 * Dd * Dd];       // [ncat][k]
__device__ __half g_Qh [2][(size_t)BSs * Dd];
__device__ __half g_Kh [2][(size_t)BSs * Dd];
__device__ __half g_Vth[(size_t)Bb * Dd * Ss];         // [b][d][tok] fp16
__device__ __half g_Ph0[(size_t)Bb * Ss * Ss];         // fp16 P, zero-padded
__device__ float  g_V  [(size_t)BSs * Dd];

#define BM 128
#define BN 128
#define BK 32
#define NT 512
#define KPAD 40
#define PLANEH (BM * KPAD)             // 5120 halves = 10240 B
#define SMEM_BYTES (3 * 4 * PLANEH * 2)   // 3 stages x up to 4 planes = 122880 B

__device__ __forceinline__ uint32_t smem_u32(const void* p) {
    uint32_t a;
    asm("{ .reg .u64 t; cvta.to.shared.u64 t, %1; cvt.u32.u64 %0, t; }" : "=r"(a) : "l"(p));
    return a;
}

__device__ __forceinline__ void cp16(uint32_t dst, const void* src) {
    asm volatile("cp.async.cg.shared.global [%0], [%1], 16;" :: "r"(dst), "l"(src));
}
__device__ __forceinline__ void cp_commit() { asm volatile("cp.async.commit_group;"); }

__device__ __forceinline__ void ldsm_x4(uint32_t* a, uint32_t addr) {
    asm volatile("ldmatrix.sync.aligned.m8n8.x4.shared.b16 {%0,%1,%2,%3}, [%4];"
                 : "=r"(a[0]), "=r"(a[1]), "=r"(a[2]), "=r"(a[3]) : "r"(addr));
}

__device__ __forceinline__ void mma16816(float* d, const uint32_t* a, const uint32_t* b) {
    asm volatile(
        "mma.sync.aligned.m16n8k16.row.col.f32.f16.f16.f32 "
        "{%0,%1,%2,%3}, {%4,%5,%6,%7}, {%8,%9}, {%0,%1,%2,%3};"
        : "+f"(d[0]), "+f"(d[1]), "+f"(d[2]), "+f"(d[3])
        : "r"(a[0]), "r"(a[1]), "r"(a[2]), "r"(a[3]), "r"(b[0]), "r"(b[1]));
}

__device__ __forceinline__ void split2(float v, __half& h0, __half& h1) {
    h0 = __float2half_rn(v);
    h1 = __float2half_rn(v - __half2float(h0));
}

// ---------------------------------------------------------------------------
// GEMM core on precomputed half planes. AP/BP = number of A/B planes (1 or 2).
// Passes: a0b0 [+ a1b0 if AP==2] [+ a0b1 if BP==2].
// 3-stage cp.async ring, ONE __syncthreads per chunk.
// 512 threads, 16 warps, 32x32 warp tiles.
// ---------------------------------------------------------------------------
template <int AP, int BP>
__device__ __forceinline__ void mma_gemm(__half* sm,
                                         const __half* __restrict__ A0,
                                         const __half* __restrict__ A1, size_t lda,
                                         const __half* __restrict__ B0,
                                         const __half* __restrict__ B1, size_t ldb,
                                         int NB, float acc[2][4][4])
{
    constexpr int NP = AP + BP;
    const int tid  = threadIdx.x;
    const int lane = tid & 31;
    const int wid  = tid >> 5;
    const int wm   = (wid & 3) * 32;
    const int wn   = (wid >> 2) * 32;

    // staging map: row rS = tid>>2 (0..127), segment sS = (tid&3)*8 halves
    const int rS = tid >> 2;
    const int sS = (tid & 3) * 8;

    const __half* srcs[NP];
    srcs[0] = A0 + (size_t)rS * lda + sS;
    if (AP == 2) srcs[1] = A1 + (size_t)rS * lda + sS;
    srcs[AP + 0] = B0 + (size_t)rS * ldb + sS;
    if (BP == 2) srcs[AP + 1] = B1 + (size_t)rS * ldb + sS;

    const uint32_t sbase = smem_u32(sm);
    const uint32_t stOff = (uint32_t)(rS * KPAD + sS) * 2;

    auto issue_chunk = [&](int c) {
        const int st = c % 3;
        const size_t ko = (size_t)c * BK;
        #pragma unroll
        for (int p = 0; p < NP; p++)
            cp16(sbase + (uint32_t)((st * NP + p) * PLANEH) * 2 + stOff,
                 srcs[p] + ko);
        cp_commit();
    };

    issue_chunk(0);
    if (NB > 1) issue_chunk(1);

    for (int c = 0; c < NB; c++) {
        // wait for chunk c's group (this thread's); then barrier for visibility
        if (c + 1 < NB) asm volatile("cp.async.wait_group 1;");
        else            asm volatile("cp.async.wait_group 0;");
        __syncthreads();
        // safe to overwrite stage (c+2)%3 == (c-1)%3: everyone passed compute(c-1)
        if (c + 2 < NB) issue_chunk(c + 2);

        const int st = c % 3;
        const uint32_t aB0 = sbase + (uint32_t)((st * NP + 0) * PLANEH) * 2;
        const uint32_t aB1 = sbase + (uint32_t)((st * NP + 1) * PLANEH) * 2;       // AP==2
        const uint32_t bB0 = sbase + (uint32_t)((st * NP + AP + 0) * PLANEH) * 2;
        const uint32_t bB1 = sbase + (uint32_t)((st * NP + AP + 1) * PLANEH) * 2;  // BP==2

        #pragma unroll
        for (int ks = 0; ks < 2; ks++) {
            uint32_t afr[2][2][4];
            const int arow = wm + (lane & 15);
            const int acol = ks*16 + (lane >> 4) * 8;
            #pragma unroll
            for (int im = 0; im < 2; im++) {
                ldsm_x4(afr[0][im], aB0 + (uint32_t)((arow + im*16)*KPAD + acol)*2);
                if (AP == 2)
                    ldsm_x4(afr[1][im], aB1 + (uint32_t)((arow + im*16)*KPAD + acol)*2);
            }
            uint32_t bfr[2][4][2];
            const int brow = lane & 7;
            const int bm   = lane >> 3;
            const int bn_o = ((bm >> 1) << 3) + brow;
            const int bk_o = ks*16 + ((bm & 1) << 3);
            #pragma unroll
            for (int g = 0; g < 2; g++) {
                const uint32_t off = (uint32_t)((wn + g*16 + bn_o) * KPAD + bk_o) * 2;
                uint32_t t0[4];
                ldsm_x4(t0, bB0 + off);
                bfr[0][g*2 + 0][0] = t0[0]; bfr[0][g*2 + 0][1] = t0[1];
                bfr[0][g*2 + 1][0] = t0[2]; bfr[0][g*2 + 1][1] = t0[3];
                if (BP == 2) {
                    uint32_t t1[4];
                    ldsm_x4(t1, bB1 + off);
                    bfr[1][g*2 + 0][0] = t1[0]; bfr[1][g*2 + 0][1] = t1[1];
                    bfr[1][g*2 + 1][0] = t1[2]; bfr[1][g*2 + 1][1] = t1[3];
                }
            }
            #pragma unroll
            for (int im = 0; im < 2; im++)
                #pragma unroll
                for (int in_ = 0; in_ < 4; in_++) {
                    mma16816(acc[im][in_], afr[0][im], bfr[0][in_]);     // a0*b0
                    if (AP == 2)
                        mma16816(acc[im][in_], afr[1][im], bfr[0][in_]); // a1*b0
                    if (BP == 2)
                        mma16816(acc[im][in_], afr[0][im], bfr[1][in_]); // a0*b1
                }
        }
    }
}

// ---------------------------------------------------------------------------
// Split kernels
// ---------------------------------------------------------------------------
__global__ __launch_bounds__(256) void split_x(const float* __restrict__ X)
{
    const size_t i = ((size_t)blockIdx.x * 256 + threadIdx.x) * 8;
    float4 v0 = *(const float4*)&X[i];
    float4 v1 = *(const float4*)&X[i + 4];
    const float v[8] = {v0.x, v0.y, v0.z, v0.w, v1.x, v1.y, v1.z, v1.w};
    __half h0[8], h1[8];
    #pragma unroll
    for (int j = 0; j < 8; j++) split2(v[j], h0[j], h1[j]);
    uint4 u0, u1;
    __half2* p0 = (__half2*)&u0;  __half2* p1 = (__half2*)&u1;
    #pragma unroll
    for (int j = 0; j < 4; j++) {
        p0[j] = __halves2half2(h0[2*j], h0[2*j+1]);
        p1[j] = __halves2half2(h1[2*j], h1[2*j+1]);
    }
    *(uint4*)&g_Xh[0][i] = u0;
    *(uint4*)&g_Xh[1][i] = u1;
}

__global__ __launch_bounds__(256) void split_wT(
    const float* __restrict__ Wq, const float* __restrict__ Wk,
    const float* __restrict__ Wv)
{
    __shared__ float s[32][33];
    const int w = blockIdx.z;
    const float* W = (w == 0) ? Wq : (w == 1) ? Wk : Wv;
    const int n0 = blockIdx.x * 32, k0 = blockIdx.y * 32;
    const int tx = threadIdx.x & 31, ty = threadIdx.x >> 5;
    #pragma unroll
    for (int i = 0; i < 4; i++)
        s[ty + i*8][tx] = W[(size_t)(k0 + ty + i*8) * Dd + n0 + tx];
    __syncthreads();
    #pragma unroll
    for (int i = 0; i < 4; i++) {
        const int n = n0 + ty + i*8;
        __half h0, h1; split2(s[tx][ty + i*8], h0, h1);
        const size_t o = (size_t)(w * Dd + n) * Dd + k0 + tx;
        g_Wth[0][o] = h0; g_Wth[1][o] = h1;
    }
}

__global__ __launch_bounds__(256) void split_vT()
{
    __shared__ float s[32][33];
    const int b = blockIdx.z;
    const int tok0 = blockIdx.x * 32, d0 = blockIdx.y * 32;
    const int tx = threadIdx.x & 31, ty = threadIdx.x >> 5;
    #pragma unroll
    for (int i = 0; i < 4; i++)
        s[ty + i*8][tx] = g_V[((size_t)b * Ss + tok0 + ty + i*8) * Dd + d0 + tx];
    __syncthreads();
    #pragma unroll
    for (int i = 0; i < 4; i++) {
        const int d = d0 + ty + i*8;
        g_Vth[(size_t)b * Dd * Ss + (size_t)d * Ss + tok0 + tx] =
            __float2half_rn(s[tx][ty + i*8]);
    }
}

// ---------------------------------------------------------------------------
// Kernel: QKV projection (3-pass).
// ---------------------------------------------------------------------------
__global__ __launch_bounds__(NT) void qkv_mma()
{
    extern __shared__ __half sm[];

    const int n0g  = blockIdx.x * BN;
    const int m0   = blockIdx.y * BM;
    const int widx = n0g >> 10;
    const int col0 = n0g & 1023;

    float acc[2][4][4] = {};
    mma_gemm<2, 2>(sm,
        g_Xh[0] + (size_t)m0 * Dd, g_Xh[1] + (size_t)m0 * Dd, Dd,
        g_Wth[0] + (size_t)n0g * Dd, g_Wth[1] + (size_t)n0g * Dd, Dd,
        Dd / BK, acc);

    const int lane = threadIdx.x & 31, wid = threadIdx.x >> 5;
    const int rb = m0 + (wid & 3)*32, cb = col0 + (wid >> 2)*32;

    if (widx < 2) {
        __half* O0 = widx ? g_Kh[0] : g_Qh[0];
        __half* O1 = widx ? g_Kh[1] : g_Qh[1];
        #pragma unroll
        for (int im = 0; im < 2; im++)
            #pragma unroll
            for (int in_ = 0; in_ < 4; in_++) {
                const int r0 = rb + im*16 + (lane >> 2);
                const int c0 = cb + in_*8 + (lane & 3)*2;
                __half a0, a1, b0, b1;
                split2(acc[im][in_][0], a0, a1);
                split2(acc[im][in_][1], b0, b1);
                *(__half2*)&O0[(size_t)r0 * Dd + c0] = __halves2half2(a0, b0);
                *(__half2*)&O1[(size_t)r0 * Dd + c0] = __halves2half2(a1, b1);
                split2(acc[im][in_][2], a0, a1);
                split2(acc[im][in_][3], b0, b1);
                *(__half2*)&O0[(size_t)(r0 + 8) * Dd + c0] = __halves2half2(a0, b0);
                *(__half2*)&O1[(size_t)(r0 + 8) * Dd + c0] = __halves2half2(a1, b1);
            }
    } else {
        #pragma unroll
        for (int im = 0; im < 2; im++)
            #pragma unroll
            for (int in_ = 0; in_ < 4; in_++) {
                const int r0 = rb + im*16 + (lane >> 2);
                const int c0 = cb + in_*8 + (lane & 3)*2;
                float2 v0 = {acc[im][in_][0], acc[im][in_][1]};
                float2 v1 = {acc[im][in_][2], acc[im][in_][3]};
                *(float2*)&g_V[(size_t)r0 * Dd + c0]       = v0;
                *(float2*)&g_V[(size_t)(r0 + 8) * Dd + c0] = v1;
            }
    }
}

// ---------------------------------------------------------------------------
// Kernel: scores = (Q.K^T)/32, causal masked (3-pass).
// ---------------------------------------------------------------------------
__global__ __launch_bounds__(NT) void scores_mma(float* __restrict__ Sout)
{
    extern __shared__ __half sm[];

    const int b  = blockIdx.z;
    const int q0 = blockIdx.y * BM;
    const int k0 = blockIdx.x * BN;
    const int tid = threadIdx.x;
    float* Sb = Sout + (size_t)b * Ss * Ss;

    if (k0 > q0 + 127) {
        const float4 z = {0.f, 0.f, 0.f, 0.f};
        for (int t = tid; t < 4096; t += NT) {
            const int r = t >> 5, c4 = (t & 31) * 4;
            *(float4*)&Sb[(size_t)(q0 + r) * Ss + k0 + c4] = z;
        }
        return;
    }

    const size_t oq = ((size_t)b * Ss + q0) * Dd;
    const size_t ok = ((size_t)b * Ss + k0) * Dd;
    float acc[2][4][4] = {};
    mma_gemm<2, 2>(sm, g_Qh[0] + oq, g_Qh[1] + oq, Dd,
                       g_Kh[0] + ok, g_Kh[1] + ok, Dd, Dd / BK, acc);

    const float scale = 0.03125f;
    const int lane = tid & 31, wid = tid >> 5;
    const int wm = (wid & 3) * 32, wn = (wid >> 2) * 32;
    #pragma unroll
    for (int im = 0; im < 2; im++)
        #pragma unroll
        for (int in_ = 0; in_ < 4; in_++) {
            const int q  = q0 + wm + im*16 + (lane >> 2);
            const int kk = k0 + wn + in_*8 + (lane & 3)*2;
            float2 v0, v1;
            v0.x = (kk   <= q)     ? acc[im][in_][0] * scale : 0.f;
            v0.y = (kk+1 <= q)     ? acc[im][in_][1] * scale : 0.f;
            v1.x = (kk   <= q + 8) ? acc[im][in_][2] * scale : 0.f;
            v1.y = (kk+1 <= q + 8) ? acc[im][in_][3] * scale : 0.f;
            *(float2*)&Sb[(size_t)q * Ss + kk]       = v0;
            *(float2*)&Sb[(size_t)(q + 8) * Ss + kk] = v1;
        }
}

// ---------------------------------------------------------------------------
// Kernel: causal row softmax in place + single fp16 P plane (zero padded).
// ---------------------------------------------------------------------------
__global__ __launch_bounds__(256) void softmax_kernel(float* __restrict__ Sc)
{
    const int row = blockIdx.x;
    const int b = row / Ss;
    const int q = row - b * Ss;
    float* r = Sc + (size_t)b * Ss * Ss + (size_t)q * Ss;
    const size_t pb = ((size_t)b * Ss + q) * Ss;
    const int len = q + 1;
    const int t = threadIdx.x;

    __shared__ float red[256];

    float vals[8];
    int n = 0;
    float m = -3.4e38f;
    for (int i = t; i < len; i += 256) { float v = r[i]; vals[n++] = v; m = fmaxf(m, v); }
    red[t] = m; __syncthreads();
    #pragma unroll
    for (int s2 = 128; s2 > 0; s2 >>= 1) {
        if (t < s2) red[t] = fmaxf(red[t], red[t + s2]);
        __syncthreads();
    }
    m = red[0]; __syncthreads();

    float sum = 0.f;
    for (int i = 0; i < n; i++) { vals[i] = __expf(vals[i] - m); sum += vals[i]; }
    red[t] = sum; __syncthreads();
    #pragma unroll
    for (int s2 = 128; s2 > 0; s2 >>= 1) {
        if (t < s2) red[t] += red[t + s2];
        __syncthreads();
    }
    const float inv = 1.0f / red[0];

    n = 0;
    for (int i = t; i < Ss; i += 256) {
        float pv = 0.0f;
        if (i < len) { pv = vals[n++] * inv; r[i] = pv; }
        g_Ph0[pb + i] = __float2half_rn(pv);
    }
}

// ---------------------------------------------------------------------------
// Kernel: context = P @ V (1-pass: P0*V0); K loop stops past diagonal.
// ---------------------------------------------------------------------------
__global__ __launch_bounds__(NT) void context_mma(float* __restrict__ Ctx)
{
    extern __shared__ __half sm[];

    const int b  = blockIdx.z;
    const int q0 = blockIdx.y * BM;
    const int n0 = blockIdx.x * BN;

    const size_t op = ((size_t)b * Ss + q0) * Ss;
    const size_t ov = (size_t)b * Dd * Ss + (size_t)n0 * Ss;
    float acc[2][4][4] = {};
    mma_gemm<1, 1>(sm, g_Ph0 + op, (const __half*)nullptr, Ss,
                       g_Vth + ov, (const __half*)nullptr, Ss,
                       q0 / BK + 4, acc);

    float* Ob = Ctx + (size_t)b * Ss * Dd;
    const int lane = threadIdx.x & 31, wid = threadIdx.x >> 5;
    const int rb = q0 + (wid & 3)*32, cb = n0 + (wid >> 2)*32;
    #pragma unroll
    for (int im = 0; im < 2; im++)
        #pragma unroll
        for (int in_ = 0; in_ < 4; in_++) {
            const int r0 = rb + im*16 + (lane >> 2);
            const int c0 = cb + in_*8 + (lane & 3)*2;
            float2 v0 = {acc[im][in_][0], acc[im][in_][1]};
            float2 v1 = {acc[im][in_][2], acc[im][in_][3]};
            *(float2*)&Ob[(size_t)r0 * Dd + c0]       = v0;
            *(float2*)&Ob[(size_t)(r0 + 8) * Dd + c0] = v1;
        }
}

// ---------------------------------------------------------------------------
extern "C" void kernel_launch(void* const* d_in, const int* in_sizes, int n_in,
                              void* d_out, int out_size)
{
    const float* x  = (const float*)d_in[0];
    const float* Wq = (const float*)d_in[1];
    const float* Wk = (const float*)d_in[2];
    const float* Wv = (const float*)d_in[3];

    float* out = (float*)d_out;
    float* ctx = out;
    float* sc  = out + (size_t)Bb * Ss * Dd;

    cudaFuncSetAttribute(qkv_mma,     cudaFuncAttributeMaxDynamicSharedMemorySize, SMEM_BYTES);
    cudaFuncSetAttribute(scores_mma,  cudaFuncAttributeMaxDynamicSharedMemorySize, SMEM_BYTES);
    cudaFuncSetAttribute(context_mma, cudaFuncAttributeMaxDynamicSharedMemorySize, SMEM_BYTES);

    split_x<<<(int)(((size_t)BSs * Dd / 8) / 256), 256>>>(x);
    split_wT<<<dim3(Dd/32, Dd/32, 3), 256>>>(Wq, Wk, Wv);

    qkv_mma<<<dim3(3 * Dd / BN, BSs / BM), NT, SMEM_BYTES>>>();
    split_vT<<<dim3(Ss/32, Dd/32, Bb), 256>>>();
    scores_mma<<<dim3(Ss / BN, Ss / BM, Bb), NT, SMEM_BYTES>>>(sc);
    softmax_kernel<<<BSs, 256>>>(sc);
    context_mma<<<dim3(Dd / BN, Ss / BM, Bb), NT, SMEM_BYTES>>>(ctx);
}